// round 4
// baseline (speedup 1.0000x reference)
#include <cuda_runtime.h>
#include <cstdint>

#define NT 16     // NUM_TYPES
#define OD 128    // OUT_DIM
#define N_MAX 100000
#define E_MAX 3200000

// Scratch (allocation-free rule: __device__ globals). 16B-aligned for float4.
__device__ __align__(16) float g_p[N_MAX * NT];
__device__ __align__(16) float g_msum[N_MAX * NT];
__device__ int g_deg_int[N_MAX];
__device__ int g_cursor[N_MAX];
__device__ int g_off[N_MAX + 1];
__device__ int g_srcsorted[E_MAX];
__device__ int g_idx64;   // 1 if indices are int64, 0 if int32

// ---------------------------------------------------------------------------
// Detect index width. int32 data misread as int64 gives values >= 2^32 with
// overwhelming probability (hi half is a random node id, rarely 0).
// ---------------------------------------------------------------------------
__global__ void k_detect(const void* __restrict__ src, int E) {
    if (blockIdx.x == 0 && threadIdx.x == 0) {
        const unsigned long long* p = (const unsigned long long*)src;
        int is64 = 1;
        int lim = (E / 2 < 16) ? E / 2 : 16;
        for (int i = 0; i < lim; i++) {
            if (p[i] > 0x7FFFFFFFULL) is64 = 0;
        }
        g_idx64 = is64;
    }
}

__device__ __forceinline__ int load_idx(const void* v, int e) {
    return g_idx64 ? (int)((const long long*)v)[e] : ((const int*)v)[e];
}

// ---------------------------------------------------------------------------
// Zero histogram + cursor
// ---------------------------------------------------------------------------
__global__ void k_zero(int n) {
    int i = blockIdx.x * blockDim.x + threadIdx.x;
    if (i < n) { g_deg_int[i] = 0; g_cursor[i] = 0; }
}

// ---------------------------------------------------------------------------
// Histogram of dst
// ---------------------------------------------------------------------------
__global__ void k_hist(const void* __restrict__ dstv, int E, int n) {
    int e = blockIdx.x * blockDim.x + threadIdx.x;
    if (e >= E) return;
    int d = load_idx(dstv, e);
    d = min(max(d, 0), n - 1);
    atomicAdd(&g_deg_int[d], 1);
}

// ---------------------------------------------------------------------------
// Exclusive scan of g_deg_int[0..n) -> g_off[0..n]. Single block, 1024 thr.
// ---------------------------------------------------------------------------
__global__ void k_scan(int n) {
    __shared__ int ssum[1024];
    int tid = threadIdx.x;
    int chunk = (n + 1023) >> 10;
    int start = tid * chunk;
    int end   = min(start + chunk, n);

    int local = 0;
    for (int i = start; i < end; i++) local += g_deg_int[i];
    ssum[tid] = local;
    __syncthreads();

    // Hillis-Steele inclusive scan
    for (int off = 1; off < 1024; off <<= 1) {
        int v = (tid >= off) ? ssum[tid - off] : 0;
        __syncthreads();
        ssum[tid] += v;
        __syncthreads();
    }

    int run = (tid == 0) ? 0 : ssum[tid - 1];
    for (int i = start; i < end; i++) {
        int v = g_deg_int[i];
        g_off[i] = run;
        run += v;
    }
    if (tid == 1023) g_off[n] = ssum[1023];
}

// ---------------------------------------------------------------------------
// Counting-sort fill: srcsorted grouped by dst
// ---------------------------------------------------------------------------
__global__ void k_fill(const void* __restrict__ srcv,
                       const void* __restrict__ dstv, int E, int n) {
    int e = blockIdx.x * blockDim.x + threadIdx.x;
    if (e >= E) return;
    int s = load_idx(srcv, e);
    int d = load_idx(dstv, e);
    s = min(max(s, 0), n - 1);
    d = min(max(d, 0), n - 1);
    int pos = g_off[d] + atomicAdd(&g_cursor[d], 1);
    g_srcsorted[pos] = s;
}

// ---------------------------------------------------------------------------
// p = softmax(relu(r@W1+b1) @ Wp + bp)   TWO nodes per thread
// W1: [16,128] row-major, Wp: [128,16] row-major
// ---------------------------------------------------------------------------
__global__ void __launch_bounds__(256) k_compute_p(
        const float* __restrict__ r,
        const float* __restrict__ W1,
        const float* __restrict__ b1,
        const float* __restrict__ Wp,
        const float* __restrict__ bp,
        int n) {
    __shared__ float sW1t[OD * NT];  // [j*16 + k] = W1[k*128 + j]
    __shared__ float sWp [OD * NT];  // [j*16 + t] = Wp[j*16 + t]
    __shared__ float sb1 [OD];
    __shared__ float sbp [NT];

    for (int i = threadIdx.x; i < OD * NT; i += blockDim.x) {
        int j = i >> 4, k = i & 15;
        sW1t[i] = W1[k * OD + j];
        sWp[i]  = Wp[i];
    }
    for (int i = threadIdx.x; i < OD; i += blockDim.x) sb1[i] = b1[i];
    if (threadIdx.x < NT) sbp[threadIdx.x] = bp[threadIdx.x];
    __syncthreads();

    int node0 = (blockIdx.x * blockDim.x + threadIdx.x) * 2;
    if (node0 >= n) return;
    bool two = (node0 + 1 < n);

    const float4* rp0 = (const float4*)(r + (size_t)node0 * NT);
    float4 a0 = rp0[0], a1 = rp0[1], a2 = rp0[2], a3 = rp0[3];
    float4 b0, b1v, b2, b3;
    if (two) {
        const float4* rp1 = (const float4*)(r + (size_t)(node0 + 1) * NT);
        b0 = rp1[0]; b1v = rp1[1]; b2 = rp1[2]; b3 = rp1[3];
    } else {
        b0 = b1v = b2 = b3 = make_float4(0.f, 0.f, 0.f, 0.f);
    }

    float accA[NT], accB[NT];
#pragma unroll
    for (int t = 0; t < NT; t++) { accA[t] = sbp[t]; accB[t] = sbp[t]; }

    const float4* w1t4 = (const float4*)sW1t;
    const float4* wp4  = (const float4*)sWp;

#pragma unroll 2
    for (int j = 0; j < OD; j++) {
        float4 wa = w1t4[j * 4 + 0];
        float4 wb = w1t4[j * 4 + 1];
        float4 wc = w1t4[j * 4 + 2];
        float4 wd = w1t4[j * 4 + 3];
        float bj = sb1[j];

        float zA = bj, zB = bj;
        zA = fmaf(a0.x, wa.x, zA); zA = fmaf(a0.y, wa.y, zA);
        zA = fmaf(a0.z, wa.z, zA); zA = fmaf(a0.w, wa.w, zA);
        zA = fmaf(a1.x, wb.x, zA); zA = fmaf(a1.y, wb.y, zA);
        zA = fmaf(a1.z, wb.z, zA); zA = fmaf(a1.w, wb.w, zA);
        zA = fmaf(a2.x, wc.x, zA); zA = fmaf(a2.y, wc.y, zA);
        zA = fmaf(a2.z, wc.z, zA); zA = fmaf(a2.w, wc.w, zA);
        zA = fmaf(a3.x, wd.x, zA); zA = fmaf(a3.y, wd.y, zA);
        zA = fmaf(a3.z, wd.z, zA); zA = fmaf(a3.w, wd.w, zA);
        zA = fmaxf(zA, 0.0f);

        zB = fmaf(b0.x, wa.x, zB); zB = fmaf(b0.y, wa.y, zB);
        zB = fmaf(b0.z, wa.z, zB); zB = fmaf(b0.w, wa.w, zB);
        zB = fmaf(b1v.x, wb.x, zB); zB = fmaf(b1v.y, wb.y, zB);
        zB = fmaf(b1v.z, wb.z, zB); zB = fmaf(b1v.w, wb.w, zB);
        zB = fmaf(b2.x, wc.x, zB); zB = fmaf(b2.y, wc.y, zB);
        zB = fmaf(b2.z, wc.z, zB); zB = fmaf(b2.w, wc.w, zB);
        zB = fmaf(b3.x, wd.x, zB); zB = fmaf(b3.y, wd.y, zB);
        zB = fmaf(b3.z, wd.z, zB); zB = fmaf(b3.w, wd.w, zB);
        zB = fmaxf(zB, 0.0f);

        float4 p0 = wp4[j * 4 + 0];
        float4 p1 = wp4[j * 4 + 1];
        float4 p2 = wp4[j * 4 + 2];
        float4 p3 = wp4[j * 4 + 3];
        accA[0]  = fmaf(zA, p0.x, accA[0]);  accB[0]  = fmaf(zB, p0.x, accB[0]);
        accA[1]  = fmaf(zA, p0.y, accA[1]);  accB[1]  = fmaf(zB, p0.y, accB[1]);
        accA[2]  = fmaf(zA, p0.z, accA[2]);  accB[2]  = fmaf(zB, p0.z, accB[2]);
        accA[3]  = fmaf(zA, p0.w, accA[3]);  accB[3]  = fmaf(zB, p0.w, accB[3]);
        accA[4]  = fmaf(zA, p1.x, accA[4]);  accB[4]  = fmaf(zB, p1.x, accB[4]);
        accA[5]  = fmaf(zA, p1.y, accA[5]);  accB[5]  = fmaf(zB, p1.y, accB[5]);
        accA[6]  = fmaf(zA, p1.z, accA[6]);  accB[6]  = fmaf(zB, p1.z, accB[6]);
        accA[7]  = fmaf(zA, p1.w, accA[7]);  accB[7]  = fmaf(zB, p1.w, accB[7]);
        accA[8]  = fmaf(zA, p2.x, accA[8]);  accB[8]  = fmaf(zB, p2.x, accB[8]);
        accA[9]  = fmaf(zA, p2.y, accA[9]);  accB[9]  = fmaf(zB, p2.y, accB[9]);
        accA[10] = fmaf(zA, p2.z, accA[10]); accB[10] = fmaf(zB, p2.z, accB[10]);
        accA[11] = fmaf(zA, p2.w, accA[11]); accB[11] = fmaf(zB, p2.w, accB[11]);
        accA[12] = fmaf(zA, p3.x, accA[12]); accB[12] = fmaf(zB, p3.x, accB[12]);
        accA[13] = fmaf(zA, p3.y, accA[13]); accB[13] = fmaf(zB, p3.y, accB[13]);
        accA[14] = fmaf(zA, p3.z, accA[14]); accB[14] = fmaf(zB, p3.z, accB[14]);
        accA[15] = fmaf(zA, p3.w, accA[15]); accB[15] = fmaf(zB, p3.w, accB[15]);
    }

    // softmax + store, node0
    {
        float m = accA[0];
#pragma unroll
        for (int t = 1; t < NT; t++) m = fmaxf(m, accA[t]);
        float s = 0.0f;
#pragma unroll
        for (int t = 0; t < NT; t++) { accA[t] = __expf(accA[t] - m); s += accA[t]; }
        float inv = 1.0f / s;
        float4* o = (float4*)(g_p + (size_t)node0 * NT);
        o[0] = make_float4(accA[0]*inv, accA[1]*inv, accA[2]*inv, accA[3]*inv);
        o[1] = make_float4(accA[4]*inv, accA[5]*inv, accA[6]*inv, accA[7]*inv);
        o[2] = make_float4(accA[8]*inv, accA[9]*inv, accA[10]*inv, accA[11]*inv);
        o[3] = make_float4(accA[12]*inv, accA[13]*inv, accA[14]*inv, accA[15]*inv);
    }
    if (two) {
        float m = accB[0];
#pragma unroll
        for (int t = 1; t < NT; t++) m = fmaxf(m, accB[t]);
        float s = 0.0f;
#pragma unroll
        for (int t = 0; t < NT; t++) { accB[t] = __expf(accB[t] - m); s += accB[t]; }
        float inv = 1.0f / s;
        float4* o = (float4*)(g_p + (size_t)(node0 + 1) * NT);
        o[0] = make_float4(accB[0]*inv, accB[1]*inv, accB[2]*inv, accB[3]*inv);
        o[1] = make_float4(accB[4]*inv, accB[5]*inv, accB[6]*inv, accB[7]*inv);
        o[2] = make_float4(accB[8]*inv, accB[9]*inv, accB[10]*inv, accB[11]*inv);
        o[3] = make_float4(accB[12]*inv, accB[13]*inv, accB[14]*inv, accB[15]*inv);
    }
}

// ---------------------------------------------------------------------------
// Atomic-free segmented gather: one warp per dst node.
// Lane (k,q): k = lane>>2 edge slot (8 per iter), q = lane&3 float4 quarter.
// ---------------------------------------------------------------------------
__global__ void k_gather(int n) {
    int wglobal = (blockIdx.x * blockDim.x + threadIdx.x) >> 5;
    if (wglobal >= n) return;
    int lane = threadIdx.x & 31;
    int k = lane >> 2, q = lane & 3;

    int beg = g_off[wglobal];
    int end = g_off[wglobal + 1];

    float4 acc = make_float4(0.f, 0.f, 0.f, 0.f);
    for (int i = beg + k; i < end; i += 8) {
        int s = g_srcsorted[i];
        const float4 v = *(const float4*)(g_p + (size_t)s * NT + q * 4);
        acc.x += v.x; acc.y += v.y; acc.z += v.z; acc.w += v.w;
    }

#pragma unroll
    for (int off = 16; off >= 4; off >>= 1) {
        acc.x += __shfl_down_sync(0xffffffffu, acc.x, off);
        acc.y += __shfl_down_sync(0xffffffffu, acc.y, off);
        acc.z += __shfl_down_sync(0xffffffffu, acc.z, off);
        acc.w += __shfl_down_sync(0xffffffffu, acc.w, off);
    }
    if (k == 0) {
        *(float4*)(g_msum + (size_t)wglobal * NT + q * 4) = acc;
    }
}

// ---------------------------------------------------------------------------
// out = relu((msum/max(deg,1)) @ Wf + bf)   one thread per output element
// deg comes from CSR offsets.
// ---------------------------------------------------------------------------
__global__ void k_final(const float* __restrict__ Wf,
                        const float* __restrict__ bf,
                        float* __restrict__ out,
                        int n) {
    __shared__ float sWft[OD * NT];  // [j*16 + t] = Wf[t*128 + j]
    __shared__ float sbf [OD];
    for (int i = threadIdx.x; i < OD * NT; i += blockDim.x) {
        int j = i >> 4, t = i & 15;
        sWft[i] = Wf[t * OD + j];
    }
    for (int i = threadIdx.x; i < OD; i += blockDim.x) sbf[i] = bf[i];
    __syncthreads();

    int total  = n * OD;
    int stride = gridDim.x * blockDim.x;
    for (int gid = blockIdx.x * blockDim.x + threadIdx.x; gid < total; gid += stride) {
        int node = gid >> 7;
        int j    = gid & 127;

        int dg = g_off[node + 1] - g_off[node];
        float invd = 1.0f / fmaxf((float)dg, 1.0f);

        const float4* ms = (const float4*)(g_msum + (size_t)node * NT);
        float4 m0 = ms[0], m1 = ms[1], m2 = ms[2], m3 = ms[3];

        const float4* w = (const float4*)(sWft + j * NT);
        float4 a = w[0], b = w[1], c = w[2], d = w[3];

        float acc = 0.0f;
        acc = fmaf(m0.x, a.x, acc); acc = fmaf(m0.y, a.y, acc);
        acc = fmaf(m0.z, a.z, acc); acc = fmaf(m0.w, a.w, acc);
        acc = fmaf(m1.x, b.x, acc); acc = fmaf(m1.y, b.y, acc);
        acc = fmaf(m1.z, b.z, acc); acc = fmaf(m1.w, b.w, acc);
        acc = fmaf(m2.x, c.x, acc); acc = fmaf(m2.y, c.y, acc);
        acc = fmaf(m2.z, c.z, acc); acc = fmaf(m2.w, c.w, acc);
        acc = fmaf(m3.x, d.x, acc); acc = fmaf(m3.y, d.y, acc);
        acc = fmaf(m3.z, d.z, acc); acc = fmaf(m3.w, d.w, acc);

        acc = fmaf(invd, acc, sbf[j]);
        out[gid] = fmaxf(acc, 0.0f);
    }
}

// ---------------------------------------------------------------------------
// Inputs (metadata order): r, src, dst, W1, b1, Wp, bp, Wf, bf
// ---------------------------------------------------------------------------
extern "C" void kernel_launch(void* const* d_in, const int* in_sizes, int n_in,
                              void* d_out, int out_size) {
    const float* r   = (const float*)d_in[0];
    const void*  src = d_in[1];
    const void*  dst = d_in[2];
    const float* W1  = (const float*)d_in[3];
    const float* b1  = (const float*)d_in[4];
    const float* Wp  = (const float*)d_in[5];
    const float* bp  = (const float*)d_in[6];
    const float* Wf  = (const float*)d_in[7];
    const float* bf  = (const float*)d_in[8];
    float*       out = (float*)d_out;

    int n = in_sizes[0] / NT;   // N nodes
    int E = in_sizes[1];        // edges
    if (n > N_MAX) n = N_MAX;
    if (E > E_MAX) E = E_MAX;

    int eblocks = (E + 255) / 256;

    k_detect<<<1, 32>>>(src, E);
    k_zero<<<(n + 255) / 256, 256>>>(n);
    k_compute_p<<<(n / 2 + 255) / 256, 256>>>(r, W1, b1, Wp, bp, n);
    k_hist<<<eblocks, 256>>>(dst, E, n);
    k_scan<<<1, 1024>>>(n);
    k_fill<<<eblocks, 256>>>(src, dst, E, n);
    {
        long long threads = (long long)n * 32;
        int blocks = (int)((threads + 255) / 256);
        k_gather<<<blocks, 256>>>(n);
    }
    k_final<<<3200, 256>>>(Wf, bf, out, n);
}

// round 5
// speedup vs baseline: 1.0973x; 1.0973x over previous
#include <cuda_runtime.h>
#include <cstdint>

#define NT 16     // NUM_TYPES
#define OD 128    // OUT_DIM
#define N_MAX 100000
#define E_MAX 3200000

// Scratch (allocation-free rule: __device__ globals). 16B-aligned for float4.
__device__ __align__(16) float g_p[N_MAX * NT];
__device__ __align__(16) float g_msum[N_MAX * NT];
__device__ int g_deg_int[N_MAX];
__device__ int g_cursor[N_MAX];     // running write cursor (init = offset)
__device__ int g_off[N_MAX + 1];
__device__ int g_srcsorted[E_MAX];
__device__ int g_idx64;   // 1 if indices are int64, 0 if int32

// ---------------------------------------------------------------------------
// Detect index width. int32 data misread as int64 gives values >= 2^32 with
// overwhelming probability (hi half is a random node id, rarely 0).
// ---------------------------------------------------------------------------
__global__ void k_detect(const void* __restrict__ src, int E) {
    if (blockIdx.x == 0 && threadIdx.x == 0) {
        const unsigned long long* p = (const unsigned long long*)src;
        int is64 = 1;
        int lim = (E / 2 < 16) ? E / 2 : 16;
        for (int i = 0; i < lim; i++) {
            if (p[i] > 0x7FFFFFFFULL) is64 = 0;
        }
        g_idx64 = is64;
    }
}

// ---------------------------------------------------------------------------
// Zero histogram
// ---------------------------------------------------------------------------
__global__ void k_zero(int n) {
    int i = blockIdx.x * blockDim.x + threadIdx.x;
    if (i < n) g_deg_int[i] = 0;
}

// ---------------------------------------------------------------------------
// Histogram of dst — 4 edges per thread, vectorized index loads
// ---------------------------------------------------------------------------
__global__ void k_hist(const void* __restrict__ dstv, int E, int n) {
    int t = blockIdx.x * blockDim.x + threadIdx.x;
    int e0 = t * 4;
    if (e0 >= E) return;

    int d[4];
    if (e0 + 3 < E) {
        if (g_idx64) {
            const longlong2* p = (const longlong2*)dstv;
            longlong2 v0 = p[(e0 >> 1) + 0];
            longlong2 v1 = p[(e0 >> 1) + 1];
            d[0] = (int)v0.x; d[1] = (int)v0.y; d[2] = (int)v1.x; d[3] = (int)v1.y;
        } else {
            int4 v = ((const int4*)dstv)[t];
            d[0] = v.x; d[1] = v.y; d[2] = v.z; d[3] = v.w;
        }
#pragma unroll
        for (int i = 0; i < 4; i++) {
            int dd = min(max(d[i], 0), n - 1);
            atomicAdd(&g_deg_int[dd], 1);
        }
    } else {
        for (int e = e0; e < E; e++) {
            int dd = g_idx64 ? (int)((const long long*)dstv)[e]
                             : ((const int*)dstv)[e];
            dd = min(max(dd, 0), n - 1);
            atomicAdd(&g_deg_int[dd], 1);
        }
    }
}

// ---------------------------------------------------------------------------
// Exclusive scan of g_deg_int[0..n) -> g_off[0..n] and g_cursor (copy).
// Single block, 1024 threads.
// ---------------------------------------------------------------------------
__global__ void k_scan(int n) {
    __shared__ int ssum[1024];
    int tid = threadIdx.x;
    int chunk = (n + 1023) >> 10;
    int start = tid * chunk;
    int end   = min(start + chunk, n);

    int local = 0;
    for (int i = start; i < end; i++) local += g_deg_int[i];
    ssum[tid] = local;
    __syncthreads();

    for (int off = 1; off < 1024; off <<= 1) {
        int v = (tid >= off) ? ssum[tid - off] : 0;
        __syncthreads();
        ssum[tid] += v;
        __syncthreads();
    }

    int run = (tid == 0) ? 0 : ssum[tid - 1];
    for (int i = start; i < end; i++) {
        int v = g_deg_int[i];
        g_off[i] = run;
        g_cursor[i] = run;
        run += v;
    }
    if (tid == 1023) g_off[n] = ssum[1023];
}

// ---------------------------------------------------------------------------
// Counting-sort fill: srcsorted grouped by dst — 4 edges/thread, vector loads
// ---------------------------------------------------------------------------
__global__ void k_fill(const void* __restrict__ srcv,
                       const void* __restrict__ dstv, int E, int n) {
    int t = blockIdx.x * blockDim.x + threadIdx.x;
    int e0 = t * 4;
    if (e0 >= E) return;

    if (e0 + 3 < E) {
        int s[4], d[4];
        if (g_idx64) {
            const longlong2* ps = (const longlong2*)srcv;
            const longlong2* pd = (const longlong2*)dstv;
            longlong2 s0 = ps[(e0 >> 1) + 0], s1 = ps[(e0 >> 1) + 1];
            longlong2 d0 = pd[(e0 >> 1) + 0], d1 = pd[(e0 >> 1) + 1];
            s[0] = (int)s0.x; s[1] = (int)s0.y; s[2] = (int)s1.x; s[3] = (int)s1.y;
            d[0] = (int)d0.x; d[1] = (int)d0.y; d[2] = (int)d1.x; d[3] = (int)d1.y;
        } else {
            int4 vs = ((const int4*)srcv)[t];
            int4 vd = ((const int4*)dstv)[t];
            s[0] = vs.x; s[1] = vs.y; s[2] = vs.z; s[3] = vs.w;
            d[0] = vd.x; d[1] = vd.y; d[2] = vd.z; d[3] = vd.w;
        }
#pragma unroll
        for (int i = 0; i < 4; i++) {
            int ss = min(max(s[i], 0), n - 1);
            int dd = min(max(d[i], 0), n - 1);
            int pos = atomicAdd(&g_cursor[dd], 1);
            g_srcsorted[pos] = ss;
        }
    } else {
        for (int e = e0; e < E; e++) {
            int ss = g_idx64 ? (int)((const long long*)srcv)[e] : ((const int*)srcv)[e];
            int dd = g_idx64 ? (int)((const long long*)dstv)[e] : ((const int*)dstv)[e];
            ss = min(max(ss, 0), n - 1);
            dd = min(max(dd, 0), n - 1);
            int pos = atomicAdd(&g_cursor[dd], 1);
            g_srcsorted[pos] = ss;
        }
    }
}

// ---------------------------------------------------------------------------
// p = softmax(relu(r@W1+b1) @ Wp + bp)   TWO nodes per thread
// Shared-weight loads are uniform-address (broadcast) -> conflict-free.
// ---------------------------------------------------------------------------
__global__ void __launch_bounds__(128) k_compute_p(
        const float* __restrict__ r,
        const float* __restrict__ W1,
        const float* __restrict__ b1,
        const float* __restrict__ Wp,
        const float* __restrict__ bp,
        int n) {
    __shared__ float sW1t[OD * NT];  // [j*16 + k] = W1[k*128 + j]
    __shared__ float sWp [OD * NT];  // [j*16 + t] = Wp[j*16 + t]
    __shared__ float sb1 [OD];
    __shared__ float sbp [NT];

    for (int i = threadIdx.x; i < OD * NT; i += blockDim.x) {
        int j = i >> 4, k = i & 15;
        sW1t[i] = W1[k * OD + j];
        sWp[i]  = Wp[i];
    }
    for (int i = threadIdx.x; i < OD; i += blockDim.x) sb1[i] = b1[i];
    if (threadIdx.x < NT) sbp[threadIdx.x] = bp[threadIdx.x];
    __syncthreads();

    int node0 = (blockIdx.x * blockDim.x + threadIdx.x) * 2;
    if (node0 >= n) return;
    bool two = (node0 + 1 < n);

    const float4* rp0 = (const float4*)(r + (size_t)node0 * NT);
    float4 a0 = rp0[0], a1 = rp0[1], a2 = rp0[2], a3 = rp0[3];
    float4 b0, b1v, b2, b3;
    if (two) {
        const float4* rp1 = (const float4*)(r + (size_t)(node0 + 1) * NT);
        b0 = rp1[0]; b1v = rp1[1]; b2 = rp1[2]; b3 = rp1[3];
    } else {
        b0 = b1v = b2 = b3 = make_float4(0.f, 0.f, 0.f, 0.f);
    }

    float accA[NT], accB[NT];
#pragma unroll
    for (int t = 0; t < NT; t++) { accA[t] = sbp[t]; accB[t] = sbp[t]; }

    const float4* w1t4 = (const float4*)sW1t;
    const float4* wp4  = (const float4*)sWp;

#pragma unroll 2
    for (int j = 0; j < OD; j++) {
        float4 wa = w1t4[j * 4 + 0];
        float4 wb = w1t4[j * 4 + 1];
        float4 wc = w1t4[j * 4 + 2];
        float4 wd = w1t4[j * 4 + 3];
        float bj = sb1[j];

        float zA = bj, zB = bj;
        zA = fmaf(a0.x, wa.x, zA); zA = fmaf(a0.y, wa.y, zA);
        zA = fmaf(a0.z, wa.z, zA); zA = fmaf(a0.w, wa.w, zA);
        zA = fmaf(a1.x, wb.x, zA); zA = fmaf(a1.y, wb.y, zA);
        zA = fmaf(a1.z, wb.z, zA); zA = fmaf(a1.w, wb.w, zA);
        zA = fmaf(a2.x, wc.x, zA); zA = fmaf(a2.y, wc.y, zA);
        zA = fmaf(a2.z, wc.z, zA); zA = fmaf(a2.w, wc.w, zA);
        zA = fmaf(a3.x, wd.x, zA); zA = fmaf(a3.y, wd.y, zA);
        zA = fmaf(a3.z, wd.z, zA); zA = fmaf(a3.w, wd.w, zA);
        zA = fmaxf(zA, 0.0f);

        zB = fmaf(b0.x, wa.x, zB); zB = fmaf(b0.y, wa.y, zB);
        zB = fmaf(b0.z, wa.z, zB); zB = fmaf(b0.w, wa.w, zB);
        zB = fmaf(b1v.x, wb.x, zB); zB = fmaf(b1v.y, wb.y, zB);
        zB = fmaf(b1v.z, wb.z, zB); zB = fmaf(b1v.w, wb.w, zB);
        zB = fmaf(b2.x, wc.x, zB); zB = fmaf(b2.y, wc.y, zB);
        zB = fmaf(b2.z, wc.z, zB); zB = fmaf(b2.w, wc.w, zB);
        zB = fmaf(b3.x, wd.x, zB); zB = fmaf(b3.y, wd.y, zB);
        zB = fmaf(b3.z, wd.z, zB); zB = fmaf(b3.w, wd.w, zB);
        zB = fmaxf(zB, 0.0f);

        float4 p0 = wp4[j * 4 + 0];
        float4 p1 = wp4[j * 4 + 1];
        float4 p2 = wp4[j * 4 + 2];
        float4 p3 = wp4[j * 4 + 3];
        accA[0]  = fmaf(zA, p0.x, accA[0]);  accB[0]  = fmaf(zB, p0.x, accB[0]);
        accA[1]  = fmaf(zA, p0.y, accA[1]);  accB[1]  = fmaf(zB, p0.y, accB[1]);
        accA[2]  = fmaf(zA, p0.z, accA[2]);  accB[2]  = fmaf(zB, p0.z, accB[2]);
        accA[3]  = fmaf(zA, p0.w, accA[3]);  accB[3]  = fmaf(zB, p0.w, accB[3]);
        accA[4]  = fmaf(zA, p1.x, accA[4]);  accB[4]  = fmaf(zB, p1.x, accB[4]);
        accA[5]  = fmaf(zA, p1.y, accA[5]);  accB[5]  = fmaf(zB, p1.y, accB[5]);
        accA[6]  = fmaf(zA, p1.z, accA[6]);  accB[6]  = fmaf(zB, p1.z, accB[6]);
        accA[7]  = fmaf(zA, p1.w, accA[7]);  accB[7]  = fmaf(zB, p1.w, accB[7]);
        accA[8]  = fmaf(zA, p2.x, accA[8]);  accB[8]  = fmaf(zB, p2.x, accB[8]);
        accA[9]  = fmaf(zA, p2.y, accA[9]);  accB[9]  = fmaf(zB, p2.y, accB[9]);
        accA[10] = fmaf(zA, p2.z, accA[10]); accB[10] = fmaf(zB, p2.z, accB[10]);
        accA[11] = fmaf(zA, p2.w, accA[11]); accB[11] = fmaf(zB, p2.w, accB[11]);
        accA[12] = fmaf(zA, p3.x, accA[12]); accB[12] = fmaf(zB, p3.x, accB[12]);
        accA[13] = fmaf(zA, p3.y, accA[13]); accB[13] = fmaf(zB, p3.y, accB[13]);
        accA[14] = fmaf(zA, p3.z, accA[14]); accB[14] = fmaf(zB, p3.z, accB[14]);
        accA[15] = fmaf(zA, p3.w, accA[15]); accB[15] = fmaf(zB, p3.w, accB[15]);
    }

    {
        float m = accA[0];
#pragma unroll
        for (int t = 1; t < NT; t++) m = fmaxf(m, accA[t]);
        float s = 0.0f;
#pragma unroll
        for (int t = 0; t < NT; t++) { accA[t] = __expf(accA[t] - m); s += accA[t]; }
        float inv = 1.0f / s;
        float4* o = (float4*)(g_p + (size_t)node0 * NT);
        o[0] = make_float4(accA[0]*inv, accA[1]*inv, accA[2]*inv, accA[3]*inv);
        o[1] = make_float4(accA[4]*inv, accA[5]*inv, accA[6]*inv, accA[7]*inv);
        o[2] = make_float4(accA[8]*inv, accA[9]*inv, accA[10]*inv, accA[11]*inv);
        o[3] = make_float4(accA[12]*inv, accA[13]*inv, accA[14]*inv, accA[15]*inv);
    }
    if (two) {
        float m = accB[0];
#pragma unroll
        for (int t = 1; t < NT; t++) m = fmaxf(m, accB[t]);
        float s = 0.0f;
#pragma unroll
        for (int t = 0; t < NT; t++) { accB[t] = __expf(accB[t] - m); s += accB[t]; }
        float inv = 1.0f / s;
        float4* o = (float4*)(g_p + (size_t)(node0 + 1) * NT);
        o[0] = make_float4(accB[0]*inv, accB[1]*inv, accB[2]*inv, accB[3]*inv);
        o[1] = make_float4(accB[4]*inv, accB[5]*inv, accB[6]*inv, accB[7]*inv);
        o[2] = make_float4(accB[8]*inv, accB[9]*inv, accB[10]*inv, accB[11]*inv);
        o[3] = make_float4(accB[12]*inv, accB[13]*inv, accB[14]*inv, accB[15]*inv);
    }
}

// ---------------------------------------------------------------------------
// Atomic-free segmented gather: one warp per dst node.
// Lane (k,q): k = lane>>2 edge slot (8 per iter), q = lane&3 float4 quarter.
// ---------------------------------------------------------------------------
__global__ void k_gather(int n) {
    int wglobal = (blockIdx.x * blockDim.x + threadIdx.x) >> 5;
    if (wglobal >= n) return;
    int lane = threadIdx.x & 31;
    int k = lane >> 2, q = lane & 3;

    int beg = g_off[wglobal];
    int end = g_off[wglobal + 1];

    float4 acc = make_float4(0.f, 0.f, 0.f, 0.f);
    for (int i = beg + k; i < end; i += 8) {
        int s = g_srcsorted[i];
        const float4 v = *(const float4*)(g_p + (size_t)s * NT + q * 4);
        acc.x += v.x; acc.y += v.y; acc.z += v.z; acc.w += v.w;
    }

#pragma unroll
    for (int off = 16; off >= 4; off >>= 1) {
        acc.x += __shfl_down_sync(0xffffffffu, acc.x, off);
        acc.y += __shfl_down_sync(0xffffffffu, acc.y, off);
        acc.z += __shfl_down_sync(0xffffffffu, acc.z, off);
        acc.w += __shfl_down_sync(0xffffffffu, acc.w, off);
    }
    if (k == 0) {
        *(float4*)(g_msum + (size_t)wglobal * NT + q * 4) = acc;
    }
}

// ---------------------------------------------------------------------------
// out = relu((msum/max(deg,1)) @ Wf + bf)
// Grid stride is a multiple of 128 -> j = tid&127 is loop-invariant:
// the 16 weights for this output column live in REGISTERS (no smem, no LDS).
// ---------------------------------------------------------------------------
__global__ void __launch_bounds__(256) k_final(
        const float* __restrict__ Wf,
        const float* __restrict__ bf,
        float* __restrict__ out,
        int n) {
    int j = threadIdx.x & 127;
    float w[NT];
#pragma unroll
    for (int t = 0; t < NT; t++) w[t] = Wf[t * OD + j];   // coalesced, L1-hot
    float bj = bf[j];

    int total  = n * OD;
    int stride = gridDim.x * blockDim.x;   // 3200*256 = 819200 = 6400*128
    for (int gid = blockIdx.x * blockDim.x + threadIdx.x; gid < total; gid += stride) {
        int node = gid >> 7;

        int dg = g_off[node + 1] - g_off[node];
        float invd = 1.0f / fmaxf((float)dg, 1.0f);

        const float4* ms = (const float4*)(g_msum + (size_t)node * NT);
        float4 m0 = ms[0], m1 = ms[1], m2 = ms[2], m3 = ms[3];

        float acc = 0.0f;
        acc = fmaf(m0.x, w[0],  acc); acc = fmaf(m0.y, w[1],  acc);
        acc = fmaf(m0.z, w[2],  acc); acc = fmaf(m0.w, w[3],  acc);
        acc = fmaf(m1.x, w[4],  acc); acc = fmaf(m1.y, w[5],  acc);
        acc = fmaf(m1.z, w[6],  acc); acc = fmaf(m1.w, w[7],  acc);
        acc = fmaf(m2.x, w[8],  acc); acc = fmaf(m2.y, w[9],  acc);
        acc = fmaf(m2.z, w[10], acc); acc = fmaf(m2.w, w[11], acc);
        acc = fmaf(m3.x, w[12], acc); acc = fmaf(m3.y, w[13], acc);
        acc = fmaf(m3.z, w[14], acc); acc = fmaf(m3.w, w[15], acc);

        acc = fmaf(invd, acc, bj);
        out[gid] = fmaxf(acc, 0.0f);
    }
}

// ---------------------------------------------------------------------------
// Inputs (metadata order): r, src, dst, W1, b1, Wp, bp, Wf, bf
// ---------------------------------------------------------------------------
extern "C" void kernel_launch(void* const* d_in, const int* in_sizes, int n_in,
                              void* d_out, int out_size) {
    const float* r   = (const float*)d_in[0];
    const void*  src = d_in[1];
    const void*  dst = d_in[2];
    const float* W1  = (const float*)d_in[3];
    const float* b1  = (const float*)d_in[4];
    const float* Wp  = (const float*)d_in[5];
    const float* bp  = (const float*)d_in[6];
    const float* Wf  = (const float*)d_in[7];
    const float* bf  = (const float*)d_in[8];
    float*       out = (float*)d_out;

    int n = in_sizes[0] / NT;   // N nodes
    int E = in_sizes[1];        // edges
    if (n > N_MAX) n = N_MAX;
    if (E > E_MAX) E = E_MAX;

    int e4blocks = ((E + 3) / 4 + 255) / 256;

    k_detect<<<1, 32>>>(src, E);
    k_zero<<<(n + 255) / 256, 256>>>(n);
    k_compute_p<<<((n + 1) / 2 + 127) / 128, 128>>>(r, W1, b1, Wp, bp, n);
    k_hist<<<e4blocks, 256>>>(dst, E, n);
    k_scan<<<1, 1024>>>(n);
    k_fill<<<e4blocks, 256>>>(src, dst, E, n);
    {
        long long threads = (long long)n * 32;
        int blocks = (int)((threads + 255) / 256);
        k_gather<<<blocks, 256>>>(n);
    }
    k_final<<<3200, 256>>>(Wf, bf, out, n);
}

// round 6
// speedup vs baseline: 1.7142x; 1.5621x over previous
#include <cuda_runtime.h>
#include <cstdint>

#define NT 16     // NUM_TYPES
#define OD 128    // OUT_DIM
#define N_MAX 100000

// Scratch (allocation-free rule: __device__ globals). 16B-aligned for float4.
__device__ __align__(16) float g_p[N_MAX * NT];
__device__ __align__(16) float g_msum[N_MAX * NT];
__device__ float g_deg[N_MAX];
__device__ int   g_idx64;   // 1 if indices are int64, 0 if int32

// ---------------------------------------------------------------------------
// Detect index width. int32 data misread as int64 gives values >= 2^32 with
// overwhelming probability (hi half would be a random node id, rarely 0).
// ---------------------------------------------------------------------------
__global__ void k_detect(const void* __restrict__ src, int E) {
    if (blockIdx.x == 0 && threadIdx.x == 0) {
        const unsigned long long* p = (const unsigned long long*)src;
        int is64 = 1;
        int lim = (E / 2 < 16) ? E / 2 : 16;
        for (int i = 0; i < lim; i++) {
            if (p[i] > 0x7FFFFFFFULL) is64 = 0;
        }
        g_idx64 = is64;
    }
}

// ---------------------------------------------------------------------------
// Zero msum + deg
// ---------------------------------------------------------------------------
__global__ void k_zero(int n) {
    int i = blockIdx.x * blockDim.x + threadIdx.x;
    int tot = n * NT;
    if (i < tot) g_msum[i] = 0.0f;
    if (i < n)   g_deg[i]  = 0.0f;
}

// ---------------------------------------------------------------------------
// p = softmax(relu(r@W1+b1) @ Wp + bp)   TWO nodes per thread
// W1: [16,128] row-major, Wp: [128,16] row-major.
// All shared-weight loads are uniform-address (warp broadcast, conflict-free).
// ---------------------------------------------------------------------------
__global__ void __launch_bounds__(128) k_compute_p(
        const float* __restrict__ r,
        const float* __restrict__ W1,
        const float* __restrict__ b1,
        const float* __restrict__ Wp,
        const float* __restrict__ bp,
        int n) {
    __shared__ float sW1t[OD * NT];  // [j*16 + k] = W1[k*128 + j]
    __shared__ float sWp [OD * NT];  // [j*16 + t] = Wp[j*16 + t]
    __shared__ float sb1 [OD];
    __shared__ float sbp [NT];

    for (int i = threadIdx.x; i < OD * NT; i += blockDim.x) {
        int j = i >> 4, k = i & 15;
        sW1t[i] = W1[k * OD + j];
        sWp[i]  = Wp[i];
    }
    for (int i = threadIdx.x; i < OD; i += blockDim.x) sb1[i] = b1[i];
    if (threadIdx.x < NT) sbp[threadIdx.x] = bp[threadIdx.x];
    __syncthreads();

    int node0 = (blockIdx.x * blockDim.x + threadIdx.x) * 2;
    if (node0 >= n) return;
    bool two = (node0 + 1 < n);

    const float4* rp0 = (const float4*)(r + (size_t)node0 * NT);
    float4 a0 = rp0[0], a1 = rp0[1], a2 = rp0[2], a3 = rp0[3];
    float4 b0, b1v, b2, b3;
    if (two) {
        const float4* rp1 = (const float4*)(r + (size_t)(node0 + 1) * NT);
        b0 = rp1[0]; b1v = rp1[1]; b2 = rp1[2]; b3 = rp1[3];
    } else {
        b0 = b1v = b2 = b3 = make_float4(0.f, 0.f, 0.f, 0.f);
    }

    float accA[NT], accB[NT];
#pragma unroll
    for (int t = 0; t < NT; t++) { accA[t] = sbp[t]; accB[t] = sbp[t]; }

    const float4* w1t4 = (const float4*)sW1t;
    const float4* wp4  = (const float4*)sWp;

#pragma unroll 2
    for (int j = 0; j < OD; j++) {
        float4 wa = w1t4[j * 4 + 0];
        float4 wb = w1t4[j * 4 + 1];
        float4 wc = w1t4[j * 4 + 2];
        float4 wd = w1t4[j * 4 + 3];
        float bj = sb1[j];

        float zA = bj, zB = bj;
        zA = fmaf(a0.x, wa.x, zA); zA = fmaf(a0.y, wa.y, zA);
        zA = fmaf(a0.z, wa.z, zA); zA = fmaf(a0.w, wa.w, zA);
        zA = fmaf(a1.x, wb.x, zA); zA = fmaf(a1.y, wb.y, zA);
        zA = fmaf(a1.z, wb.z, zA); zA = fmaf(a1.w, wb.w, zA);
        zA = fmaf(a2.x, wc.x, zA); zA = fmaf(a2.y, wc.y, zA);
        zA = fmaf(a2.z, wc.z, zA); zA = fmaf(a2.w, wc.w, zA);
        zA = fmaf(a3.x, wd.x, zA); zA = fmaf(a3.y, wd.y, zA);
        zA = fmaf(a3.z, wd.z, zA); zA = fmaf(a3.w, wd.w, zA);
        zA = fmaxf(zA, 0.0f);

        zB = fmaf(b0.x, wa.x, zB); zB = fmaf(b0.y, wa.y, zB);
        zB = fmaf(b0.z, wa.z, zB); zB = fmaf(b0.w, wa.w, zB);
        zB = fmaf(b1v.x, wb.x, zB); zB = fmaf(b1v.y, wb.y, zB);
        zB = fmaf(b1v.z, wb.z, zB); zB = fmaf(b1v.w, wb.w, zB);
        zB = fmaf(b2.x, wc.x, zB); zB = fmaf(b2.y, wc.y, zB);
        zB = fmaf(b2.z, wc.z, zB); zB = fmaf(b2.w, wc.w, zB);
        zB = fmaf(b3.x, wd.x, zB); zB = fmaf(b3.y, wd.y, zB);
        zB = fmaf(b3.z, wd.z, zB); zB = fmaf(b3.w, wd.w, zB);
        zB = fmaxf(zB, 0.0f);

        float4 p0 = wp4[j * 4 + 0];
        float4 p1 = wp4[j * 4 + 1];
        float4 p2 = wp4[j * 4 + 2];
        float4 p3 = wp4[j * 4 + 3];
        accA[0]  = fmaf(zA, p0.x, accA[0]);  accB[0]  = fmaf(zB, p0.x, accB[0]);
        accA[1]  = fmaf(zA, p0.y, accA[1]);  accB[1]  = fmaf(zB, p0.y, accB[1]);
        accA[2]  = fmaf(zA, p0.z, accA[2]);  accB[2]  = fmaf(zB, p0.z, accB[2]);
        accA[3]  = fmaf(zA, p0.w, accA[3]);  accB[3]  = fmaf(zB, p0.w, accB[3]);
        accA[4]  = fmaf(zA, p1.x, accA[4]);  accB[4]  = fmaf(zB, p1.x, accB[4]);
        accA[5]  = fmaf(zA, p1.y, accA[5]);  accB[5]  = fmaf(zB, p1.y, accB[5]);
        accA[6]  = fmaf(zA, p1.z, accA[6]);  accB[6]  = fmaf(zB, p1.z, accB[6]);
        accA[7]  = fmaf(zA, p1.w, accA[7]);  accB[7]  = fmaf(zB, p1.w, accB[7]);
        accA[8]  = fmaf(zA, p2.x, accA[8]);  accB[8]  = fmaf(zB, p2.x, accB[8]);
        accA[9]  = fmaf(zA, p2.y, accA[9]);  accB[9]  = fmaf(zB, p2.y, accB[9]);
        accA[10] = fmaf(zA, p2.z, accA[10]); accB[10] = fmaf(zB, p2.z, accB[10]);
        accA[11] = fmaf(zA, p2.w, accA[11]); accB[11] = fmaf(zB, p2.w, accB[11]);
        accA[12] = fmaf(zA, p3.x, accA[12]); accB[12] = fmaf(zB, p3.x, accB[12]);
        accA[13] = fmaf(zA, p3.y, accA[13]); accB[13] = fmaf(zB, p3.y, accB[13]);
        accA[14] = fmaf(zA, p3.z, accA[14]); accB[14] = fmaf(zB, p3.z, accB[14]);
        accA[15] = fmaf(zA, p3.w, accA[15]); accB[15] = fmaf(zB, p3.w, accB[15]);
    }

    {
        float m = accA[0];
#pragma unroll
        for (int t = 1; t < NT; t++) m = fmaxf(m, accA[t]);
        float s = 0.0f;
#pragma unroll
        for (int t = 0; t < NT; t++) { accA[t] = __expf(accA[t] - m); s += accA[t]; }
        float inv = 1.0f / s;
        float4* o = (float4*)(g_p + (size_t)node0 * NT);
        o[0] = make_float4(accA[0]*inv, accA[1]*inv, accA[2]*inv, accA[3]*inv);
        o[1] = make_float4(accA[4]*inv, accA[5]*inv, accA[6]*inv, accA[7]*inv);
        o[2] = make_float4(accA[8]*inv, accA[9]*inv, accA[10]*inv, accA[11]*inv);
        o[3] = make_float4(accA[12]*inv, accA[13]*inv, accA[14]*inv, accA[15]*inv);
    }
    if (two) {
        float m = accB[0];
#pragma unroll
        for (int t = 1; t < NT; t++) m = fmaxf(m, accB[t]);
        float s = 0.0f;
#pragma unroll
        for (int t = 0; t < NT; t++) { accB[t] = __expf(accB[t] - m); s += accB[t]; }
        float inv = 1.0f / s;
        float4* o = (float4*)(g_p + (size_t)(node0 + 1) * NT);
        o[0] = make_float4(accB[0]*inv, accB[1]*inv, accB[2]*inv, accB[3]*inv);
        o[1] = make_float4(accB[4]*inv, accB[5]*inv, accB[6]*inv, accB[7]*inv);
        o[2] = make_float4(accB[8]*inv, accB[9]*inv, accB[10]*inv, accB[11]*inv);
        o[3] = make_float4(accB[12]*inv, accB[13]*inv, accB[14]*inv, accB[15]*inv);
    }
}

// ---------------------------------------------------------------------------
// Scatter: msum[dst] += p[src], deg[dst] += 1.  4 threads per edge,
// scalar f32 REDs (no vector fp32 RED on sm_100a). Measured 134us in R3.
// ---------------------------------------------------------------------------
__global__ void k_scatter(const void* __restrict__ srcv,
                          const void* __restrict__ dstv,
                          int E, int n) {
    int gid = blockIdx.x * blockDim.x + threadIdx.x;
    int e = gid >> 2;
    if (e >= E) return;
    int q = gid & 3;

    int s, d;
    if (g_idx64) {
        s = (int)((const long long*)srcv)[e];
        d = (int)((const long long*)dstv)[e];
    } else {
        s = ((const int*)srcv)[e];
        d = ((const int*)dstv)[e];
    }
    s = min(max(s, 0), n - 1);
    d = min(max(d, 0), n - 1);

    const float4 v = __ldg((const float4*)(g_p + (size_t)s * NT + q * 4));
    float* dp = g_msum + (size_t)d * NT + q * 4;
    atomicAdd(dp + 0, v.x);
    atomicAdd(dp + 1, v.y);
    atomicAdd(dp + 2, v.z);
    atomicAdd(dp + 3, v.w);
    if (q == 0) {
        atomicAdd(g_deg + d, 1.0f);
    }
}

// ---------------------------------------------------------------------------
// out = relu((msum/max(deg,1)) @ Wf + bf)
// Grid stride is a multiple of 128 -> j = tid&127 is loop-invariant:
// the 16 weights for this column live in REGISTERS. No smem, no conflicts.
// ---------------------------------------------------------------------------
__global__ void __launch_bounds__(256) k_final(
        const float* __restrict__ Wf,
        const float* __restrict__ bf,
        float* __restrict__ out,
        int n) {
    int j = threadIdx.x & 127;
    float w[NT];
#pragma unroll
    for (int t = 0; t < NT; t++) w[t] = Wf[t * OD + j];   // coalesced, L1-hot
    float bj = bf[j];

    int total  = n * OD;
    int stride = gridDim.x * blockDim.x;   // 3200*256 multiple of 128
    for (int gid = blockIdx.x * blockDim.x + threadIdx.x; gid < total; gid += stride) {
        int node = gid >> 7;

        float invd = 1.0f / fmaxf(g_deg[node], 1.0f);

        const float4* ms = (const float4*)(g_msum + (size_t)node * NT);
        float4 m0 = ms[0], m1 = ms[1], m2 = ms[2], m3 = ms[3];

        float acc = 0.0f;
        acc = fmaf(m0.x, w[0],  acc); acc = fmaf(m0.y, w[1],  acc);
        acc = fmaf(m0.z, w[2],  acc); acc = fmaf(m0.w, w[3],  acc);
        acc = fmaf(m1.x, w[4],  acc); acc = fmaf(m1.y, w[5],  acc);
        acc = fmaf(m1.z, w[6],  acc); acc = fmaf(m1.w, w[7],  acc);
        acc = fmaf(m2.x, w[8],  acc); acc = fmaf(m2.y, w[9],  acc);
        acc = fmaf(m2.z, w[10], acc); acc = fmaf(m2.w, w[11], acc);
        acc = fmaf(m3.x, w[12], acc); acc = fmaf(m3.y, w[13], acc);
        acc = fmaf(m3.z, w[14], acc); acc = fmaf(m3.w, w[15], acc);

        acc = fmaf(invd, acc, bj);
        out[gid] = fmaxf(acc, 0.0f);
    }
}

// ---------------------------------------------------------------------------
// Inputs (metadata order): r, src, dst, W1, b1, Wp, bp, Wf, bf
// ---------------------------------------------------------------------------
extern "C" void kernel_launch(void* const* d_in, const int* in_sizes, int n_in,
                              void* d_out, int out_size) {
    const float* r   = (const float*)d_in[0];
    const void*  src = d_in[1];
    const void*  dst = d_in[2];
    const float* W1  = (const float*)d_in[3];
    const float* b1  = (const float*)d_in[4];
    const float* Wp  = (const float*)d_in[5];
    const float* bp  = (const float*)d_in[6];
    const float* Wf  = (const float*)d_in[7];
    const float* bf  = (const float*)d_in[8];
    float*       out = (float*)d_out;

    int n = in_sizes[0] / NT;   // N nodes
    int E = in_sizes[1];        // edges
    if (n > N_MAX) n = N_MAX;

    k_detect<<<1, 32>>>(src, E);
    {
        int tot = n * NT;
        k_zero<<<(tot + 255) / 256, 256>>>(n);
    }
    k_compute_p<<<((n + 1) / 2 + 127) / 128, 128>>>(r, W1, b1, Wp, bp, n);
    {
        long long threads = (long long)E * 4;
        int blocks = (int)((threads + 255) / 256);
        k_scatter<<<blocks, 256>>>(src, dst, E, n);
    }
    k_final<<<3200, 256>>>(Wf, bf, out, n);
}